// round 17
// baseline (speedup 1.0000x reference)
#include <cuda_runtime.h>
#include <cuda_fp16.h>
#include <stdint.h>
#include <math.h>

#define T_TOK 2048
#define H_DIM 2048
#define I_DIM 1024
#define N_EXP 16
#define TOPK  4
#define NGRP  4
#define GSZ   4
#define SCALING 2.5f

#define STAGE_BYTES 20480u
#define N_STAGES    4
#define SMEM_DYN    (N_STAGES * STAGE_BYTES)   // 81920 -> 2 CTAs/SM

#define ROUTE_TB    8                           // tokens per route block
#define ROUTE_SMEM  (ROUTE_TB * H_DIM * 4 + ROUTE_TB * N_EXP * 4)

// ---------------------------------------------------------------------------
// Scratch (device globals). Everything plain fp16.
// ---------------------------------------------------------------------------
__device__ int   d_counts[N_EXP];
__device__ int   d_tok[N_EXP][T_TOK];
__device__ float d_wgt[N_EXP][T_TOK];
__device__ __half d_h1 [N_EXP][T_TOK][I_DIM];
__device__ __half d_h1s[T_TOK][I_DIM];
__device__ __half d_x16[T_TOK * H_DIM];
__device__ __half d_gp16[N_EXP * I_DIM * H_DIM];
__device__ __half d_up16[N_EXP * I_DIM * H_DIM];
__device__ __half d_dp16[N_EXP * H_DIM * I_DIM];
__device__ __half d_sg16[I_DIM * H_DIM];
__device__ __half d_su16[I_DIM * H_DIM];
__device__ __half d_sd16[H_DIM * I_DIM];

// ---------------------------------------------------------------------------
// PTX helpers (baseline sm_80+ only)
// ---------------------------------------------------------------------------
__device__ __forceinline__ uint32_t smem_u32(const void* p) {
    uint32_t a;
    asm("{ .reg .u64 t; cvta.to.shared.u64 t, %1; cvt.u32.u64 %0, t; }"
        : "=r"(a) : "l"(p));
    return a;
}

__device__ __forceinline__ void ldm_x4(uint32_t addr, uint32_t r[4]) {
    asm volatile("ldmatrix.sync.aligned.m8n8.x4.shared.b16 {%0,%1,%2,%3}, [%4];"
                 : "=r"(r[0]), "=r"(r[1]), "=r"(r[2]), "=r"(r[3]) : "r"(addr));
}

__device__ __forceinline__ void mma_f16(float d[4], const uint32_t a[4],
                                        uint32_t b0, uint32_t b1) {
    asm volatile(
        "mma.sync.aligned.m16n8k16.row.col.f32.f16.f16.f32 "
        "{%0,%1,%2,%3}, {%4,%5,%6,%7}, {%8,%9}, {%0,%1,%2,%3};"
        : "+f"(d[0]), "+f"(d[1]), "+f"(d[2]), "+f"(d[3])
        : "r"(a[0]), "r"(a[1]), "r"(a[2]), "r"(a[3]), "r"(b0), "r"(b1));
}

#define CP_ASYNC16(dst, src) \
    asm volatile("cp.async.cg.shared.global [%0], [%1], 16;" \
                 :: "r"(dst), "l"(src) : "memory")
#define CP_COMMIT()  asm volatile("cp.async.commit_group;" ::: "memory")
#define CP_WAIT2()   asm volatile("cp.async.wait_group 2;" ::: "memory")

__device__ __forceinline__ uint32_t pack2(float f0, float f1) {
    __half h0 = __float2half_rn(f0);
    __half h1 = __float2half_rn(f1);
    return (uint32_t)__half_as_ushort(h0) | ((uint32_t)__half_as_ushort(h1) << 16);
}

__device__ __forceinline__ uint32_t ldrel(uint32_t plane, int rbase, int lane) {
    int row = rbase + (lane & 15);
    int col = (lane >> 4) << 3;
    return plane + (uint32_t)((row * 40 + col) << 1);
}

// ---------------------------------------------------------------------------
// Weight conversion kernels (two-phase for pipelining)
// ---------------------------------------------------------------------------
#define EXP_F4   524288
#define G0_F4    (4 * EXP_F4)

__global__ __launch_bounds__(256) void split_first_kernel(
    const float4* __restrict__ sg, const float4* __restrict__ su,
    const float4* __restrict__ gp, const float4* __restrict__ up)
{
    int i = blockIdx.x * blockDim.x + threadIdx.x;
    const int stride = gridDim.x * blockDim.x;
    const int total = 2 * EXP_F4 + 2 * G0_F4;
    for (; i < total; i += stride) {
        const float4* src; uint2* h16; int off;
        if (i < EXP_F4)              { src = sg; off = i;                      h16 = (uint2*)d_sg16; }
        else if (i < 2 * EXP_F4)     { src = su; off = i - EXP_F4;             h16 = (uint2*)d_su16; }
        else if (i < 2*EXP_F4+G0_F4) { src = gp; off = i - 2 * EXP_F4;         h16 = (uint2*)d_gp16; }
        else                         { src = up; off = i - 2 * EXP_F4 - G0_F4; h16 = (uint2*)d_up16; }
        float4 f = src[off];
        uint2 h; h.x = pack2(f.x, f.y); h.y = pack2(f.z, f.w);
        h16[off] = h;
    }
}

__global__ __launch_bounds__(256) void split_rest_kernel(
    const float4* __restrict__ gp, const float4* __restrict__ up)
{
    int i = blockIdx.x * blockDim.x + threadIdx.x;
    const int stride = gridDim.x * blockDim.x;
    const int per = 12 * EXP_F4;
    for (; i < 2 * per; i += stride) {
        const float4* src; uint2* h16; int off;
        if (i < per) { src = gp; off = G0_F4 + i;       h16 = (uint2*)d_gp16; }
        else         { src = up; off = G0_F4 + i - per; h16 = (uint2*)d_up16; }
        float4 f = src[off];
        uint2 h; h.x = pack2(f.x, f.y); h.y = pack2(f.z, f.w);
        h16[off] = h;
    }
}

#define DN_DP 8388608
#define DN_SD 8912896

__global__ __launch_bounds__(256) void split_dn_kernel(
    const float4* __restrict__ dp, const float4* __restrict__ sd)
{
    int i = blockIdx.x * blockDim.x + threadIdx.x;
    const int stride = gridDim.x * blockDim.x;
    for (; i < DN_SD; i += stride) {
        const float4* src; uint2* h16; int off;
        if (i < DN_DP) { src = dp; off = i;          h16 = (uint2*)d_dp16; }
        else           { src = sd; off = i - DN_DP;  h16 = (uint2*)d_sd16; }
        float4 f = src[off];
        uint2 h; h.x = pack2(f.x, f.y); h.y = pack2(f.z, f.w);
        h16[off] = h;
    }
}

__global__ __launch_bounds__(256) void zero_out_kernel(float4* __restrict__ out, int n4)
{
    int i = blockIdx.x * blockDim.x + threadIdx.x;
    int stride = gridDim.x * blockDim.x;
    float4 z = {0.f, 0.f, 0.f, 0.f};
    for (; i < n4; i += stride) out[i] = z;
}

__global__ void zero_counts_kernel() {
    if (threadIdx.x < N_EXP) d_counts[threadIdx.x] = 0;
}

// ---------------------------------------------------------------------------
// Routing v2: 8 tokens/block. x rows staged in smem; each gw element is
// loaded once and FMAed against all 8 tokens (8x less gw traffic).
// Also emits the fp16 copy of x.
// ---------------------------------------------------------------------------
__global__ __launch_bounds__(256) void route_kernel(
    const float* __restrict__ x, const float* __restrict__ gw,
    const float* __restrict__ bias)
{
    extern __shared__ float rsm[];               // xs[8][H_DIM] then logits[8][16]
    float* xs = rsm;
    float* logits = rsm + ROUTE_TB * H_DIM;

    const int tid = threadIdx.x;
    const int t0 = blockIdx.x * ROUTE_TB;

    // stage 8 token rows (fp32)
    const float4* xsrc = (const float4*)(x + (size_t)t0 * H_DIM);
    float4* xdst = (float4*)xs;
    for (int i = tid; i < ROUTE_TB * H_DIM / 4; i += 256) xdst[i] = xsrc[i];
    __syncthreads();

    // emit fp16 copy
    {
        uint32_t* dst = (uint32_t*)(d_x16 + (size_t)t0 * H_DIM);
        for (int i = tid; i < ROUTE_TB * H_DIM / 2; i += 256)
            dst[i] = pack2(xs[i * 2], xs[i * 2 + 1]);
    }

    // logits: e = tid>>4 (expert), lane = tid&15
    const int e = tid >> 4, lane = tid & 15;
    const float* g = gw + (size_t)e * H_DIM;
    float s[ROUTE_TB];
    #pragma unroll
    for (int t = 0; t < ROUTE_TB; t++) s[t] = 0.f;
    for (int k = lane; k < H_DIM; k += 16) {
        float gv = g[k];
        #pragma unroll
        for (int t = 0; t < ROUTE_TB; t++) s[t] += xs[t * H_DIM + k] * gv;
    }
    #pragma unroll
    for (int t = 0; t < ROUTE_TB; t++) {
        float v = s[t];
        #pragma unroll
        for (int o = 8; o > 0; o >>= 1) v += __shfl_down_sync(0xffffffffu, v, o, 16);
        if (lane == 0) logits[t * N_EXP + e] = v;
    }
    __syncthreads();

    // top-k per token (one thread each)
    if (tid < ROUTE_TB) {
        const int t = t0 + tid;
        float sc[N_EXP], bs[N_EXP];
        #pragma unroll
        for (int i = 0; i < N_EXP; i++) {
            sc[i] = 1.f / (1.f + expf(-logits[tid * N_EXP + i]));
            bs[i] = sc[i] + bias[i];
        }
        float gsc[NGRP];
        #pragma unroll
        for (int gi = 0; gi < NGRP; gi++) {
            float m1 = -1e30f, m2 = -1e30f;
            #pragma unroll
            for (int j = 0; j < GSZ; j++) {
                float v = bs[gi * GSZ + j];
                if (v > m1) { m2 = m1; m1 = v; } else if (v > m2) { m2 = v; }
            }
            gsc[gi] = m1 + m2;
        }
        int g1 = 0;
        for (int gi = 1; gi < NGRP; gi++) if (gsc[gi] > gsc[g1]) g1 = gi;
        int g2 = -1;
        for (int gi = 0; gi < NGRP; gi++) {
            if (gi == g1) continue;
            if (g2 < 0 || gsc[gi] > gsc[g2]) g2 = gi;
        }
        bool allowed[N_EXP], used[N_EXP];
        #pragma unroll
        for (int i = 0; i < N_EXP; i++) {
            int gi = i / GSZ;
            allowed[i] = (gi == g1 || gi == g2);
            used[i] = false;
        }
        int sel[TOPK]; float wv[TOPK]; float wsum = 0.f;
        #pragma unroll
        for (int kk = 0; kk < TOPK; kk++) {
            int best = -1; float bv = -1e30f;
            for (int i = 0; i < N_EXP; i++) {
                if (!allowed[i] || used[i]) continue;
                if (best < 0 || bs[i] > bv) { best = i; bv = bs[i]; }
            }
            used[best] = true; sel[kk] = best; wv[kk] = sc[best]; wsum += sc[best];
        }
        const float inv = SCALING / (wsum + 1e-20f);
        #pragma unroll
        for (int kk = 0; kk < TOPK; kk++) {
            int ee = sel[kk];
            int slot = atomicAdd(&d_counts[ee], 1);
            d_tok[ee][slot] = t;
            d_wgt[ee][slot] = wv[kk] * inv;
        }
    }
}

// ---------------------------------------------------------------------------
// GEMM1: 256 threads (8 warps = 4m x 2n), CTA tile M=128 x N=64 x BK=32.
// 2 CTAs/SM. e = e_base + blockIdx.z; z==shared_z -> shared expert.
// ---------------------------------------------------------------------------
__global__ __launch_bounds__(256, 2) void gemm1_mma(int e_base, int shared_z)
{
    int e = e_base + blockIdx.z;
    if ((int)blockIdx.z == shared_z) e = N_EXP;
    const bool shared = (e == N_EXP);
    const int ne = shared ? T_TOK : d_counts[e];
    const int m0 = blockIdx.y * 128;
    if (m0 >= ne) return;
    const int n0 = blockIdx.x * 64;

    extern __shared__ __align__(16) char dynsmem[];
    __shared__ int toks[128];

    const int tid = threadIdx.x, lane = tid & 31, wid = tid >> 5;
    const int wm = wid >> 1, wn = wid & 1;
    const uint32_t sb = smem_u32(dynsmem);

    if (tid < 128) {
        int r = m0 + tid;
        toks[tid] = shared ? r : (r < ne ? d_tok[e][r] : d_tok[e][0]);
    }
    __syncthreads();

    const size_t eoff = shared ? 0 : (size_t)e * I_DIM * H_DIM;
    const __half* gP = shared ? d_sg16 : d_gp16 + eoff;
    const __half* uP = shared ? d_su16 : d_up16 + eoff;

    const int a0R = tid >> 2,          a0C = tid & 3;
    const int a1R = (tid + 256) >> 2,  a1C = tid & 3;
    const uint32_t dstA0 = (uint32_t)(a0R * 80 + a0C * 16);
    const uint32_t dstA1 = (uint32_t)(a1R * 80 + a1C * 16);
    const int bRr = tid >> 2, bCc = tid & 3;
    const uint32_t dstG = (uint32_t)(10240 + bRr * 80 + bCc * 16);
    const uint32_t dstU = dstG + 5120u;
    const __half* xPtr0 = d_x16 + (size_t)toks[a0R] * H_DIM + a0C * 8;
    const __half* xPtr1 = d_x16 + (size_t)toks[a1R] * H_DIM + a1C * 8;
    const __half* gPtr = gP + (size_t)(n0 + bRr) * H_DIM + bCc * 8;
    const __half* uPtr = uP + (size_t)(n0 + bRr) * H_DIM + bCc * 8;

    uint32_t rA[2], rG[2], rU[2];
    #pragma unroll
    for (int mi = 0; mi < 2; mi++)
        rA[mi] = ldrel(0u, wm * 32 + mi * 16, lane);
    #pragma unroll
    for (int j = 0; j < 2; j++) {
        rG[j] = ldrel(10240u, wn * 32 + j * 16, lane);
        rU[j] = ldrel(15360u, wn * 32 + j * 16, lane);
    }

    auto issue = [&](int kt) {
        const uint32_t st = sb + (uint32_t)(kt & 3) * STAGE_BYTES;
        CP_ASYNC16(st + dstA0, xPtr0); xPtr0 += 32;
        CP_ASYNC16(st + dstA1, xPtr1); xPtr1 += 32;
        CP_ASYNC16(st + dstG,  gPtr);  gPtr  += 32;
        CP_ASYNC16(st + dstU,  uPtr);  uPtr  += 32;
    };

    float cg[2][4][4] = {}, cu[2][4][4] = {};

    issue(0); CP_COMMIT();
    issue(1); CP_COMMIT();
    issue(2); CP_COMMIT();

    const int NK = H_DIM / 32;
    #pragma unroll 1
    for (int kt = 0; kt < NK; ++kt) {
        CP_WAIT2();
        __syncthreads();
        if (kt + 3 < NK) issue(kt + 3);
        CP_COMMIT();

        const uint32_t cur = sb + (uint32_t)(kt & 3) * STAGE_BYTES;
        #pragma unroll
        for (int kk = 0; kk < 2; ++kk) {
            const uint32_t kb = cur + (uint32_t)(kk * 32);
            uint32_t a[2][4], g0[4], g1[4], u0[4], u1[4];
            #pragma unroll
            for (int mi = 0; mi < 2; mi++)
                ldm_x4(kb + rA[mi], a[mi]);
            ldm_x4(kb + rG[0], g0); ldm_x4(kb + rG[1], g1);
            ldm_x4(kb + rU[0], u0); ldm_x4(kb + rU[1], u1);
            uint32_t bg[4][2] = {{g0[0],g0[2]},{g0[1],g0[3]},{g1[0],g1[2]},{g1[1],g1[3]}};
            uint32_t bu[4][2] = {{u0[0],u0[2]},{u0[1],u0[3]},{u1[0],u1[2]},{u1[1],u1[3]}};

            #pragma unroll
            for (int mi = 0; mi < 2; mi++)
                #pragma unroll
                for (int ni = 0; ni < 4; ni++)
                    mma_f16(cg[mi][ni], a[mi], bg[ni][0], bg[ni][1]);
            #pragma unroll
            for (int mi = 0; mi < 2; mi++)
                #pragma unroll
                for (int ni = 0; ni < 4; ni++)
                    mma_f16(cu[mi][ni], a[mi], bu[ni][0], bu[ni][1]);
        }
    }

    const int gr = lane >> 2, tc = (lane & 3) * 2;
    __half* ph = shared ? &d_h1s[0][0] : &d_h1[e][0][0];

    #pragma unroll
    for (int mi = 0; mi < 2; mi++)
        #pragma unroll
        for (int ni = 0; ni < 4; ni++) {
            int ncol = n0 + wn * 32 + ni * 8 + tc;
            #pragma unroll
            for (int half = 0; half < 2; half++) {
                int m = m0 + wm * 32 + mi * 16 + gr + half * 8;
                float g0 = cg[mi][ni][half * 2],     u0 = cu[mi][ni][half * 2];
                float g1 = cg[mi][ni][half * 2 + 1], u1 = cu[mi][ni][half * 2 + 1];
                float o0 = (g0 / (1.f + expf(-g0))) * u0;
                float o1 = (g1 / (1.f + expf(-g1))) * u1;
                *(uint32_t*)(ph + (size_t)m * I_DIM + ncol) = pack2(o0, o1);
            }
        }
}

// ---------------------------------------------------------------------------
// GEMM2: 256 threads (8 warps = 4m x 2n), CTA tile M=128 x N=128 x BK=32.
// 2 CTAs/SM. Atomic scatter. e = e_base + blockIdx.z; z==shared_z -> shared.
// ---------------------------------------------------------------------------
__global__ __launch_bounds__(256, 2) void gemm2_mma(float* __restrict__ out,
                                                    int e_base, int shared_z)
{
    int e = e_base + blockIdx.z;
    if ((int)blockIdx.z == shared_z) e = N_EXP;
    const bool shared = (e == N_EXP);
    const int ne = shared ? T_TOK : d_counts[e];
    const int m0 = blockIdx.y * 128;
    if (m0 >= ne) return;
    const int n0 = blockIdx.x * 128;

    extern __shared__ __align__(16) char dynsmem[];
    __shared__ int   toks[128];
    __shared__ float wgts[128];

    const int tid = threadIdx.x, lane = tid & 31, wid = tid >> 5;
    const int wm = wid >> 1, wn = wid & 1;
    const uint32_t sb = smem_u32(dynsmem);

    if (tid < 128) {
        int r = m0 + tid;
        if (shared) { toks[tid] = r; wgts[tid] = 1.f; }
        else {
            toks[tid] = (r < ne) ? d_tok[e][r] : 0;
            wgts[tid] = (r < ne) ? d_wgt[e][r] : 0.f;
        }
    }
    __syncthreads();

    const __half* ah1 = shared ? &d_h1s[0][0] : &d_h1[e][0][0];
    const size_t eoff = shared ? 0 : (size_t)e * H_DIM * I_DIM;
    const __half* dw = shared ? d_sd16 : d_dp16 + eoff;

    const int a0R = tid >> 2,         a0C = tid & 3;
    const int a1R = (tid + 256) >> 2, a1C = tid & 3;
    const uint32_t dstA0 = (uint32_t)(a0R * 80 + a0C * 16);
    const uint32_t dstA1 = (uint32_t)(a1R * 80 + a1C * 16);
    const uint32_t dstB0 = dstA0 + 10240u;
    const uint32_t dstB1 = dstA1 + 10240u;
    const __half* aPtr0 = ah1 + (size_t)(m0 + a0R) * I_DIM + a0C * 8;
    const __half* aPtr1 = ah1 + (size_t)(m0 + a1R) * I_DIM + a1C * 8;
    const __half* bPtr0 = dw + (size_t)(n0 + a0R) * I_DIM + a0C * 8;
    const __half* bPtr1 = dw + (size_t)(n0 + a1R) * I_DIM + a1C * 8;

    uint32_t rA[2], rB[4];
    #pragma unroll
    for (int mi = 0; mi < 2; mi++)
        rA[mi] = ldrel(0u, wm * 32 + mi * 16, lane);
    #pragma unroll
    for (int j = 0; j < 4; j++)
        rB[j] = ldrel(10240u, wn * 64 + j * 16, lane);

    auto issue = [&](int kt) {
        const uint32_t st = sb + (uint32_t)(kt & 3) * STAGE_BYTES;
        CP_ASYNC16(st + dstA0, aPtr0); aPtr0 += 32;
        CP_ASYNC16(st + dstA1, aPtr1); aPtr1 += 32;
        CP_ASYNC16(st + dstB0, bPtr0); bPtr0 += 32;
        CP_ASYNC16(st + dstB1, bPtr1); bPtr1 += 32;
    };

    float cd[2][8][4] = {};

    issue(0); CP_COMMIT();
    issue(1); CP_COMMIT();
    issue(2); CP_COMMIT();

    const int NK = I_DIM / 32;
    #pragma unroll 1
    for (int kt = 0; kt < NK; ++kt) {
        CP_WAIT2();
        __syncthreads();
        if (kt + 3 < NK) issue(kt + 3);
        CP_COMMIT();

        const uint32_t cur = sb + (uint32_t)(kt & 3) * STAGE_BYTES;
        #pragma unroll
        for (int kk = 0; kk < 2; ++kk) {
            const uint32_t kb = cur + (uint32_t)(kk * 32);
            uint32_t a[2][4], h[4][4];
            #pragma unroll
            for (int mi = 0; mi < 2; mi++)
                ldm_x4(kb + rA[mi], a[mi]);
            #pragma unroll
            for (int j = 0; j < 4; j++)
                ldm_x4(kb + rB[j], h[j]);
            uint32_t bh[8][2];
            #pragma unroll
            for (int j = 0; j < 4; j++) {
                bh[j*2][0]   = h[j][0]; bh[j*2][1]   = h[j][2];
                bh[j*2+1][0] = h[j][1]; bh[j*2+1][1] = h[j][3];
            }
            #pragma unroll
            for (int mi = 0; mi < 2; mi++)
                #pragma unroll
                for (int ni = 0; ni < 8; ni++)
                    mma_f16(cd[mi][ni], a[mi], bh[ni][0], bh[ni][1]);
        }
    }

    const int gr = lane >> 2, tc = (lane & 3) * 2;
    #pragma unroll
    for (int mi = 0; mi < 2; mi++) {
        #pragma unroll
        for (int half = 0; half < 2; half++) {
            int mloc = wm * 32 + mi * 16 + gr + half * 8;
            if (m0 + mloc >= ne) continue;
            int   t = toks[mloc];
            float w = wgts[mloc];
            float* orow = out + (size_t)t * H_DIM;
            #pragma unroll
            for (int ni = 0; ni < 8; ni++) {
                int ncol = n0 + wn * 64 + ni * 8 + tc;
                atomicAdd(orow + ncol,     w * cd[mi][ni][half * 2]);
                atomicAdd(orow + ncol + 1, w * cd[mi][ni][half * 2 + 1]);
            }
        }
    }
}

// ---------------------------------------------------------------------------
// Launch — 2 streams + 6 events:
//   default: zero_counts [eFork] -> route -> wait(eG0) -> gemm1 A [eC1A]
//            -> wait(eGU) -> gemm1 B -> wait(eG2A) -> gemm2 B
//   s1: wait(eFork) -> split_first [eG0] -> split_rest [eGU]
//   s2: wait(eFork) -> zero_out -> wait(eG0) -> split_dn [eDown]
//       -> wait(eC1A) -> gemm2 A (experts 0-3 + shared) [eG2A]
//   gemm2 A runs concurrently with gemm1 B (fills tensor tails).
// ---------------------------------------------------------------------------
extern "C" void kernel_launch(void* const* d_in, const int* in_sizes, int n_in,
                              void* d_out, int out_size)
{
    const float* x  = (const float*)d_in[0];
    const float* gw = (const float*)d_in[1];
    const float* eb = (const float*)d_in[2];
    const float* gp = (const float*)d_in[3];
    const float* up = (const float*)d_in[4];
    const float* dp = (const float*)d_in[5];
    const float* sg = (const float*)d_in[6];
    const float* su = (const float*)d_in[7];
    const float* sd = (const float*)d_in[8];
    float* out = (float*)d_out;

    static cudaStream_t s1, s2;
    static cudaEvent_t eFork, eG0, eGU, eDown, eC1A, eG2A;
    static bool init = false;
    if (!init) {
        cudaFuncSetAttribute((const void*)gemm1_mma, cudaFuncAttributeMaxDynamicSharedMemorySize, SMEM_DYN);
        cudaFuncSetAttribute((const void*)gemm2_mma, cudaFuncAttributeMaxDynamicSharedMemorySize, SMEM_DYN);
        cudaFuncSetAttribute((const void*)route_kernel, cudaFuncAttributeMaxDynamicSharedMemorySize, ROUTE_SMEM);
        cudaStreamCreateWithFlags(&s1, cudaStreamNonBlocking);
        cudaStreamCreateWithFlags(&s2, cudaStreamNonBlocking);
        cudaEventCreateWithFlags(&eFork, cudaEventDisableTiming);
        cudaEventCreateWithFlags(&eG0,   cudaEventDisableTiming);
        cudaEventCreateWithFlags(&eGU,   cudaEventDisableTiming);
        cudaEventCreateWithFlags(&eDown, cudaEventDisableTiming);
        cudaEventCreateWithFlags(&eC1A,  cudaEventDisableTiming);
        cudaEventCreateWithFlags(&eG2A,  cudaEventDisableTiming);
        init = true;
    }

    // default: counters, fork
    zero_counts_kernel<<<1, 32>>>();
    cudaEventRecord(eFork, 0);

    // s1: two-phase gate/up conversion
    cudaStreamWaitEvent(s1, eFork, 0);
    split_first_kernel<<<1536, 256, 0, s1>>>((const float4*)sg, (const float4*)su,
                                             (const float4*)gp, (const float4*)up);
    cudaEventRecord(eG0, s1);
    split_rest_kernel<<<3072, 256, 0, s1>>>((const float4*)gp, (const float4*)up);
    cudaEventRecord(eGU, s1);

    // s2: zero out (no deps) then down-weight conversion (after bw frees up)
    cudaStreamWaitEvent(s2, eFork, 0);
    zero_out_kernel<<<1024, 256, 0, s2>>>((float4*)out, out_size / 4);
    cudaStreamWaitEvent(s2, eG0, 0);
    split_dn_kernel<<<2048, 256, 0, s2>>>((const float4*)dp, (const float4*)sd);
    cudaEventRecord(eDown, s2);

    // default: routing (concurrent with split_first)
    route_kernel<<<T_TOK / ROUTE_TB, 256, ROUTE_SMEM>>>(x, gw, eb);

    // default: gemm1 chunk A (experts 0-3 + shared)
    cudaStreamWaitEvent(0, eG0, 0);
    gemm1_mma<<<dim3(I_DIM / 64, T_TOK / 128, 5), 256, SMEM_DYN>>>(0, 4);
    cudaEventRecord(eC1A, 0);

    // default: gemm1 chunk B (experts 4-15)
    cudaStreamWaitEvent(0, eGU, 0);
    gemm1_mma<<<dim3(I_DIM / 64, T_TOK / 128, 12), 256, SMEM_DYN>>>(4, -1);

    // s2: gemm2 chunk A (experts 0-3 + shared), concurrent with gemm1 chunk B
    cudaStreamWaitEvent(s2, eC1A, 0);
    gemm2_mma<<<dim3(H_DIM / 128, T_TOK / 128, 5), 256, SMEM_DYN, s2>>>(out, 0, 4);
    cudaEventRecord(eG2A, s2);

    // default: gemm2 chunk B (experts 4-15) after gemm1 B (order) + gemm2 A
    cudaStreamWaitEvent(0, eG2A, 0);
    gemm2_mma<<<dim3(H_DIM / 128, T_TOK / 128, 12), 256, SMEM_DYN>>>(out, 4, -1);
}